// round 7
// baseline (speedup 1.0000x reference)
#include <cuda_runtime.h>

#define TLEN 256
#define FULLMASK 0xffffffffu

// output segment offsets (floats); order: z, mu, Sig, a, A_t, B_t, C_t
#define OFF_Z   0u
#define OFF_MU  2097152u
#define OFF_SIG 4194304u
#define OFF_A   71303168u
#define OFF_AT  72351744u
#define OFF_BT  139460608u
#define OFF_CT  156237824u

struct SW {                    // shared weights, built once per CTA
    float4 AmT[1024];          // [k*32+row] = (A0..A3)[row][k]
    float4 CmS[512];           // [flat]     = (C0..C3).flat
    float4 BmS[256];           // [flat]
    float4 BmT[256];           // [j*32+row] = (B0..B3)[row][j]
    float  QT[1024];           // [j*32+row] = Q[row][j]
    float  Wh[64 * 192];
    float  Wx[32 * 192];
    float4 Wo4[64];            // [hh] = Wo[hh][0..3]
    float  bhs[192];
    float  bxs[192];
};
struct SC {                    // per-chain scratch (one warp)
    float Ls[32 * 36];         // L rows (broadcast reads)
    float Gs[32 * 36];         // G rows (broadcast reads)
    float As[32 * 33];         // A_t rows (scalar, conflict-free)
    float Ss[32 * 33];         // S rows (own-lane readback)
    float Cts[32 * 17];        // [col][row<16] C_t transposed
};
struct SAll { SW w; SC c[2]; };

__device__ __forceinline__ float fast_tanh(float x) {
    float y; asm("tanh.approx.f32 %0, %1;" : "=f"(y) : "f"(x)); return y;
}
__device__ __forceinline__ float fast_sigmoid(float x) {
    return 0.5f + 0.5f * fast_tanh(0.5f * x);
}
__device__ __forceinline__ float mix4(float4 v, float a0, float a1, float a2, float a3) {
    return fmaf(v.x, a0, fmaf(v.y, a1, fmaf(v.z, a2, v.w * a3)));
}

// lane = row. In: a[] = own S row. Out: Ls rows (upper zeroed), returns
// z = zinit + L @ eps.
__device__ __forceinline__ float chol_ls(float a[32], float eps_own, float zinit,
                                         int lane, float* Ls)
{
    float zacc = zinit;
#pragma unroll
    for (int j = 0; j < 32; ++j) {
        float d   = __shfl_sync(FULLMASK, a[j], j);
        float rs  = rsqrtf(d);
        float lij = a[j] * rs;
        a[j] = lij;
        float ej = __shfl_sync(FULLMASK, eps_own, j);
        if (lane >= j) zacc = fmaf(lij, ej, zacc);
        float lsq = lij * lij;
#pragma unroll
        for (int k = j + 1; k < 32; ++k) {
            float lkj = __shfl_sync(FULLMASK, lij, k);
            if (k == lane) a[k] -= lsq;        // own diag: off the shfl chain
            else           a[k] = fmaf(-lij, lkj, a[k]);
        }
    }
#pragma unroll
    for (int k = 0; k < 32; ++k) if (k > lane) a[k] = 0.f;
#pragma unroll
    for (int i = 0; i < 8; ++i)
        *(float4*)&Ls[lane * 36 + 4 * i] =
            make_float4(a[4*i], a[4*i+1], a[4*i+2], a[4*i+3]);
    return zacc;
}

__global__ void __launch_bounds__(64, 1)
lgssm_kernel(const float* __restrict__ mu0,   const float* __restrict__ Sig0,
             const float* __restrict__ alpha0,const float* __restrict__ h0,
             const float* __restrict__ u_f,   const float* __restrict__ eps_g,
             const float* __restrict__ Ab,    const float* __restrict__ Bb,
             const float* __restrict__ Cb,    const float* __restrict__ Qm,
             const float* __restrict__ Wx,    const float* __restrict__ Wh,
             const float* __restrict__ bx,    const float* __restrict__ bh,
             const float* __restrict__ Wo,    const float* __restrict__ bo,
             float* __restrict__ out)
{
    if (blockIdx.x >= 128) return;
    extern __shared__ float smem_f[];
    SAll& sh = *reinterpret_cast<SAll*>(smem_f);

    const int tid  = threadIdx.x;
    const int lane = tid & 31;
    const int wid  = tid >> 5;

    // ---- build weight tables (64 threads, one-time) ------------------------
    for (int i = tid; i < 1024; i += 64) {
        int k = i >> 5, row = i & 31, e = row * 32 + k;
        sh.w.AmT[i] = make_float4(Ab[e], Ab[1024 + e], Ab[2048 + e], Ab[3072 + e]);
        sh.w.QT[i]  = Qm[e];
    }
    for (int i = tid; i < 512; i += 64)
        sh.w.CmS[i] = make_float4(Cb[i], Cb[512 + i], Cb[1024 + i], Cb[1536 + i]);
    for (int i = tid; i < 256; i += 64) {
        sh.w.BmS[i] = make_float4(Bb[i], Bb[256 + i], Bb[512 + i], Bb[768 + i]);
        int j = i >> 5, row = i & 31, e = row * 8 + j;
        sh.w.BmT[i] = make_float4(Bb[e], Bb[256 + e], Bb[512 + e], Bb[768 + e]);
    }
    for (int i = tid; i < 64 * 192; i += 64) sh.w.Wh[i] = Wh[i];
    for (int i = tid; i < 32 * 192; i += 64) sh.w.Wx[i] = Wx[i];
    if (tid < 64) sh.w.Wo4[tid] = make_float4(Wo[tid*4], Wo[tid*4+1], Wo[tid*4+2], Wo[tid*4+3]);
    for (int i = tid; i < 192; i += 64) { sh.w.bhs[i] = bh[i]; sh.w.bxs[i] = bx[i]; }
    __syncthreads();

    // ---- per-chain state (lane = row) ---------------------------------------
    SC& C = sh.c[wid];
    const unsigned b = (unsigned)blockIdx.x * 2u + (unsigned)wid;

    float mu_own = mu0[b * 32u + lane];
    float al0 = alpha0[b*4u+0], al1 = alpha0[b*4u+1];
    float al2 = alpha0[b*4u+2], al3 = alpha0[b*4u+3];
    float hown0 = h0[b*64u + lane], hown1 = h0[b*64u + 32 + lane];
    float bo0 = bo[0], bo1 = bo[1], bo2 = bo[2], bo3 = bo[3];

    {   // L0 = chol(Sigma0)
        float a[32];
#pragma unroll
        for (int i = 0; i < 8; ++i) {
            float4 v = *(const float4*)(Sig0 + b * 1024u + (unsigned)(lane * 32 + 4 * i));
            a[4*i] = v.x; a[4*i+1] = v.y; a[4*i+2] = v.z; a[4*i+3] = v.w;
        }
        (void)chol_ls(a, 0.f, 0.f, lane, C.Ls);
    }
    float ep_cur = eps_g[(b * TLEN) * 32u + lane];
    float u_cur  = (lane < 8) ? u_f[(b * TLEN) * 8u + lane] : 0.f;
    __syncwarp();

#pragma unroll 1
    for (int t = 0; t < TLEN; ++t) {
        const unsigned bt  = b * TLEN + (unsigned)t;
        const unsigned btn = bt + (t < TLEN - 1 ? 1u : 0u);
        float ep_nxt = eps_g[btn * 32u + lane];                  // prefetch
        float u_nxt  = (lane < 8) ? u_f[btn * 8u + lane] : 0.f;

        __syncwarp();   // prior iteration's cross-lane reads done before rewrites

        // ---- mixtures ------------------------------------------------------
#pragma unroll 8
        for (int k = 0; k < 32; ++k)
            C.As[lane * 33 + k] = mix4(sh.w.AmT[k * 32 + lane], al0, al1, al2, al3);
#pragma unroll 4
        for (int e = 0; e < 16; ++e) {
            float cvv = mix4(sh.w.CmS[e * 32 + lane], al0, al1, al2, al3);
            C.Cts[lane * 17 + e] = cvv;
            out[OFF_CT + bt * 512u + (unsigned)(e * 32 + lane)] = cvv;
        }
#pragma unroll
        for (int e = 0; e < 8; ++e)
            out[OFF_BT + bt * 256u + (unsigned)(e * 32 + lane)] =
                mix4(sh.w.BmS[e * 32 + lane], al0, al1, al2, al3);
        __syncwarp();

        // ---- A_t output (coalesced via transposed smem read) ----------------
#pragma unroll 8
        for (int j = 0; j < 32; ++j)
            out[OFF_AT + bt * 1024u + (unsigned)(j * 32 + lane)] = C.As[j * 33 + lane];

        // ---- mu_next = A_t mu + B_t u ---------------------------------------
        float mu_new;
        {
            float m0 = 0.f, m1 = 0.f;
#pragma unroll 8
            for (int k = 0; k < 32; k += 2) {
                m0 = fmaf(C.As[lane*33 + k],     __shfl_sync(FULLMASK, mu_own, k),     m0);
                m1 = fmaf(C.As[lane*33 + k + 1], __shfl_sync(FULLMASK, mu_own, k + 1), m1);
            }
#pragma unroll
            for (int j = 0; j < 8; ++j) {
                float bj = mix4(sh.w.BmT[j * 32 + lane], al0, al1, al2, al3);
                m0 = fmaf(bj, __shfl_sync(FULLMASK, u_cur, j), m0);
            }
            mu_new = m0 + m1;
            out[OFF_MU + bt * 32u + lane] = mu_new;
        }

        // ---- G = A_t @ L (own row accumulators, L rows broadcast) -----------
        float g[32];
#pragma unroll
        for (int j = 0; j < 32; ++j) g[j] = 0.f;
#pragma unroll 4
        for (int k = 0; k < 32; ++k) {
            float ak = C.As[lane * 33 + k];
            const float4* Lr = (const float4*)&C.Ls[k * 36];
#pragma unroll
            for (int i = 0; i < 8; ++i) {
                float4 lv = Lr[i];
                g[4*i+0] = fmaf(ak, lv.x, g[4*i+0]);
                g[4*i+1] = fmaf(ak, lv.y, g[4*i+1]);
                g[4*i+2] = fmaf(ak, lv.z, g[4*i+2]);
                g[4*i+3] = fmaf(ak, lv.w, g[4*i+3]);
            }
        }
#pragma unroll
        for (int i = 0; i < 8; ++i)
            *(float4*)&C.Gs[lane * 36 + 4 * i] =
                make_float4(g[4*i], g[4*i+1], g[4*i+2], g[4*i+3]);
        __syncwarp();

        // ---- S = G G^T + Q; coalesced Sigma store; own row -> Ss ------------
#pragma unroll 2
        for (int j = 0; j < 32; ++j) {
            const float4* Gr = (const float4*)&C.Gs[j * 36];
            float a0 = 0.f, a1 = 0.f, a2 = 0.f, a3 = 0.f;
#pragma unroll
            for (int i = 0; i < 8; ++i) {
                float4 gv = Gr[i];
                a0 = fmaf(g[4*i+0], gv.x, a0);
                a1 = fmaf(g[4*i+1], gv.y, a1);
                a2 = fmaf(g[4*i+2], gv.z, a2);
                a3 = fmaf(g[4*i+3], gv.w, a3);
            }
            float sj = (a0 + a1) + (a2 + a3) + sh.w.QT[j * 32 + lane];
            C.Ss[lane * 33 + j] = sj;
            out[OFF_SIG + bt * 1024u + (unsigned)(j * 32 + lane)] = sj;
        }

        // ---- gh = h @ Wh + bh (g = lane + 32m; interleaves with chol) -------
        float gha[6];
#pragma unroll
        for (int m = 0; m < 6; ++m) gha[m] = sh.w.bhs[lane + 32 * m];
#pragma unroll 4
        for (int hh = 0; hh < 32; ++hh) {
            float hv = __shfl_sync(FULLMASK, hown0, hh);
            const float* wr = &sh.w.Wh[hh * 192 + lane];
#pragma unroll
            for (int m = 0; m < 6; ++m) gha[m] = fmaf(hv, wr[32 * m], gha[m]);
        }
#pragma unroll 4
        for (int hh = 0; hh < 32; ++hh) {
            float hv = __shfl_sync(FULLMASK, hown1, hh);
            const float* wr = &sh.w.Wh[(hh + 32) * 192 + lane];
#pragma unroll
            for (int m = 0; m < 6; ++m) gha[m] = fmaf(hv, wr[32 * m], gha[m]);
        }

        // ---- chol(S) -> Ls, fused z = mu_new + L @ eps ----------------------
        float z_own;
        {
            float a[32];
#pragma unroll
            for (int k = 0; k < 32; ++k) a[k] = C.Ss[lane * 33 + k];
            z_own = chol_ls(a, ep_cur, mu_new, lane, C.Ls);
        }
        __syncwarp();

        out[OFF_Z + bt * 32u + lane] = z_own;
        mu_own = mu_new;

        // ---- a_t = C_t z (Cts transposed, conflict-free) --------------------
        {
            float acc = 0.f;
#pragma unroll 8
            for (int k = 0; k < 32; ++k) {
                float zk = __shfl_sync(FULLMASK, z_own, k);
                acc = fmaf(C.Cts[k * 17 + (lane & 15)], zk, acc);
            }
            if (lane < 16) out[OFF_A + bt * 16u + lane] = acc;
        }

        // ---- gx = z @ Wx + bx ------------------------------------------------
        float gxa[6];
#pragma unroll
        for (int m = 0; m < 6; ++m) gxa[m] = sh.w.bxs[lane + 32 * m];
#pragma unroll 4
        for (int k = 0; k < 32; ++k) {
            float zk = __shfl_sync(FULLMASK, z_own, k);
            const float* wr = &sh.w.Wx[k * 192 + lane];
#pragma unroll
            for (int m = 0; m < 6; ++m) gxa[m] = fmaf(zk, wr[32 * m], gxa[m]);
        }

        // ---- GRU (register-local gates) + softmax (replicated) --------------
        {
            float r0 = fast_sigmoid(gxa[0] + gha[0]);
            float r1 = fast_sigmoid(gxa[1] + gha[1]);
            float zg0 = fast_sigmoid(gxa[2] + gha[2]);
            float zg1 = fast_sigmoid(gxa[3] + gha[3]);
            float n0 = fast_tanh(gxa[4] + r0 * gha[4]);
            float n1 = fast_tanh(gxa[5] + r1 * gha[5]);
            hown0 = (1.f - zg0) * n0 + zg0 * hown0;
            hown1 = (1.f - zg1) * n1 + zg1 * hown1;

            float4 w0 = sh.w.Wo4[lane], w1 = sh.w.Wo4[lane + 32];
            float p0 = fmaf(hown0, w0.x, hown1 * w1.x);
            float p1 = fmaf(hown0, w0.y, hown1 * w1.y);
            float p2 = fmaf(hown0, w0.z, hown1 * w1.z);
            float p3 = fmaf(hown0, w0.w, hown1 * w1.w);
#pragma unroll
            for (int off = 16; off; off >>= 1) {
                p0 += __shfl_xor_sync(FULLMASK, p0, off);
                p1 += __shfl_xor_sync(FULLMASK, p1, off);
                p2 += __shfl_xor_sync(FULLMASK, p2, off);
                p3 += __shfl_xor_sync(FULLMASK, p3, off);
            }
            float o0 = p0 + bo0, o1 = p1 + bo1, o2 = p2 + bo2, o3 = p3 + bo3;
            float mx = fmaxf(fmaxf(o0, o1), fmaxf(o2, o3));
            float e0 = __expf(o0 - mx), e1 = __expf(o1 - mx);
            float e2 = __expf(o2 - mx), e3 = __expf(o3 - mx);
            float inv = 1.f / (e0 + e1 + e2 + e3);
            al0 = e0 * inv; al1 = e1 * inv; al2 = e2 * inv; al3 = e3 * inv;
        }

        ep_cur = ep_nxt;
        u_cur  = u_nxt;
    }
}

extern "C" void kernel_launch(void* const* d_in, const int* in_sizes, int n_in,
                              void* d_out, int out_size)
{
    size_t shbytes = sizeof(SAll);
    cudaFuncSetAttribute(lgssm_kernel,
                         cudaFuncAttributeMaxDynamicSharedMemorySize, (int)shbytes);
    lgssm_kernel<<<148, 64, shbytes>>>(
        (const float*)d_in[0],  (const float*)d_in[1],  (const float*)d_in[2],
        (const float*)d_in[3],  (const float*)d_in[4],  (const float*)d_in[5],
        (const float*)d_in[6],  (const float*)d_in[7],  (const float*)d_in[8],
        (const float*)d_in[9],  (const float*)d_in[10], (const float*)d_in[11],
        (const float*)d_in[12], (const float*)d_in[13], (const float*)d_in[14],
        (const float*)d_in[15], (float*)d_out);
}

// round 8
// speedup vs baseline: 1.0823x; 1.0823x over previous
#include <cuda_runtime.h>

#define TLEN 256
#define FULLMASK 0xffffffffu

// output segment offsets (floats); order: z, mu, Sig, a, A_t, B_t, C_t
#define OFF_Z   0u
#define OFF_MU  2097152u
#define OFF_SIG 4194304u
#define OFF_A   71303168u
#define OFF_AT  72351744u
#define OFF_BT  139460608u
#define OFF_CT  156237824u

struct SW {                    // weights, built once per CTA (shared by 2 chains)
    float4 AmT[1024];          // [k*32+row] = (A0..A3)[row][k]
    float4 CmS[512];           // [flat]
    float4 BmS[256];           // [flat]
    float4 BmT[256];           // [j*32+row]
    float  QT[1024];           // [j*32+row] = Q[row][j]
    float  Wh[64 * 192];
    float  Wx[32 * 192];
    float4 Wo4[64];
    float  bhs[192], bxs[192];
};
struct SC {                    // per-chain scratch
    float Ls[32 * 36];         // L rows
    float Gs[32 * 36];         // G rows (cols 0-15 by W0, 16-31 by W1)
    float As[32 * 33];
    float Ss0[32 * 33];        // S partial k<16  (W0)
    float Ss1[32 * 33];        // S partial k>=16 (W1)
    float Cts[32 * 17];        // [c][r] = C_t[r][c]
    float gxs[192];
    float alsh[4];
};
struct SAll { SW w; SC c[2]; };

__device__ __forceinline__ float fast_tanh(float x) {
    float y; asm("tanh.approx.f32 %0, %1;" : "=f"(y) : "f"(x)); return y;
}
__device__ __forceinline__ float fast_sigmoid(float x) {
    return 0.5f + 0.5f * fast_tanh(0.5f * x);
}
__device__ __forceinline__ float mix4(float4 v, float a0, float a1, float a2, float a3) {
    return fmaf(v.x, a0, fmaf(v.y, a1, fmaf(v.z, a2, v.w * a3)));
}

// lane = row. a[] = own S row in; L rows out to Ls (upper zeroed).
// Returns z = zinit + L @ eps.
__device__ __forceinline__ float chol_ls(float a[32], float eps_own, float zinit,
                                         int lane, float* Ls)
{
    float zacc = zinit;
#pragma unroll
    for (int j = 0; j < 32; ++j) {
        float d   = __shfl_sync(FULLMASK, a[j], j);
        float rs  = rsqrtf(d);
        float lij = a[j] * rs;
        a[j] = lij;
        float ej = __shfl_sync(FULLMASK, eps_own, j);
        if (lane >= j) zacc = fmaf(lij, ej, zacc);
        float lsq = lij * lij;
#pragma unroll
        for (int k = j + 1; k < 32; ++k) {
            float lkj = __shfl_sync(FULLMASK, lij, k);
            if (k == lane) a[k] -= lsq;
            else           a[k] = fmaf(-lij, lkj, a[k]);
        }
    }
#pragma unroll
    for (int k = 0; k < 32; ++k) if (k > lane) a[k] = 0.f;
#pragma unroll
    for (int i = 0; i < 8; ++i)
        *(float4*)&Ls[lane * 36 + 4 * i] =
            make_float4(a[4*i], a[4*i+1], a[4*i+2], a[4*i+3]);
    return zacc;
}

__global__ void __launch_bounds__(128, 1)
lgssm_kernel(const float* __restrict__ mu0,   const float* __restrict__ Sig0,
             const float* __restrict__ alpha0,const float* __restrict__ h0,
             const float* __restrict__ u_f,   const float* __restrict__ eps_g,
             const float* __restrict__ Ab,    const float* __restrict__ Bb,
             const float* __restrict__ Cb,    const float* __restrict__ Qm,
             const float* __restrict__ Wx,    const float* __restrict__ Wh,
             const float* __restrict__ bx,    const float* __restrict__ bh,
             const float* __restrict__ Wo,    const float* __restrict__ bo,
             float* __restrict__ out)
{
    extern __shared__ float smem_f[];
    SAll& sh = *reinterpret_cast<SAll*>(smem_f);

    const int tid   = threadIdx.x;
    const int lane  = tid & 31;
    const int wid   = tid >> 5;     // 0..3
    const int chain = wid >> 1;     // 0/1
    const int cw    = wid & 1;      // 0 = spine, 1 = helper
    const int barid = chain + 1;
    SC& C = sh.c[chain];
    const unsigned b = (unsigned)blockIdx.x * 2u + (unsigned)chain;

#define CBAR() asm volatile("bar.sync %0, 64;" :: "r"(barid) : "memory")

    // ---- one-time weight tables (128 threads) -------------------------------
    for (int i = tid; i < 1024; i += 128) {
        int k = i >> 5, row = i & 31, e = row * 32 + k;
        sh.w.AmT[i] = make_float4(Ab[e], Ab[1024 + e], Ab[2048 + e], Ab[3072 + e]);
        sh.w.QT[i]  = Qm[e];
    }
    for (int i = tid; i < 512; i += 128)
        sh.w.CmS[i] = make_float4(Cb[i], Cb[512 + i], Cb[1024 + i], Cb[1536 + i]);
    for (int i = tid; i < 256; i += 128) {
        sh.w.BmS[i] = make_float4(Bb[i], Bb[256 + i], Bb[512 + i], Bb[768 + i]);
        int j = i >> 5, row = i & 31, e = row * 8 + j;
        sh.w.BmT[i] = make_float4(Bb[e], Bb[256 + e], Bb[512 + e], Bb[768 + e]);
    }
    for (int i = tid; i < 64 * 192; i += 128) sh.w.Wh[i] = Wh[i];
    for (int i = tid; i < 32 * 192; i += 128) sh.w.Wx[i] = Wx[i];
    if (tid < 64) sh.w.Wo4[tid] = make_float4(Wo[tid*4], Wo[tid*4+1], Wo[tid*4+2], Wo[tid*4+3]);
    for (int i = tid; i < 192; i += 128) { sh.w.bhs[i] = bh[i]; sh.w.bxs[i] = bx[i]; }
    __syncthreads();

    // ---- per-chain state ----------------------------------------------------
    float al0 = alpha0[b*4u+0], al1 = alpha0[b*4u+1];
    float al2 = alpha0[b*4u+2], al3 = alpha0[b*4u+3];
    float mu_own = 0.f, ep_cur = 0.f, u_cur = 0.f;
    float hown0 = 0.f, hown1 = 0.f, bo0 = 0.f, bo1 = 0.f, bo2 = 0.f, bo3 = 0.f;

    if (cw == 0) {
        mu_own = mu0[b * 32u + lane];
        float a[32];
#pragma unroll
        for (int i = 0; i < 8; ++i) {
            float4 v = *(const float4*)(Sig0 + b * 1024u + (unsigned)(lane * 32 + 4 * i));
            a[4*i] = v.x; a[4*i+1] = v.y; a[4*i+2] = v.z; a[4*i+3] = v.w;
        }
        (void)chol_ls(a, 0.f, 0.f, lane, C.Ls);
        ep_cur = eps_g[(b * TLEN) * 32u + lane];
        u_cur  = (lane < 8) ? u_f[(b * TLEN) * 8u + lane] : 0.f;
    } else {
        hown0 = h0[b*64u + lane]; hown1 = h0[b*64u + 32 + lane];
        bo0 = bo[0]; bo1 = bo[1]; bo2 = bo[2]; bo3 = bo[3];
    }
    CBAR();

#pragma unroll 1
    for (int t = 0; t < TLEN; ++t) {
        const unsigned bt  = b * TLEN + (unsigned)t;
        const unsigned btn = bt + (t < TLEN - 1 ? 1u : 0u);
        float ar[32], g[16], sreg[32], gha[6];
        float mu_new = 0.f, z_own = 0.f, ep_nxt = 0.f, u_nxt = 0.f;

        // ===== phase 0: mixtures ==============================================
        if (cw == 0) {
            ep_nxt = eps_g[btn * 32u + lane];                    // prefetch
            u_nxt  = (lane < 8) ? u_f[btn * 8u + lane] : 0.f;
#pragma unroll 8
            for (int k = 0; k < 32; ++k) {
                ar[k] = mix4(sh.w.AmT[k * 32 + lane], al0, al1, al2, al3);
                C.As[lane * 33 + k] = ar[k];
            }
        } else {
#pragma unroll 4
            for (int e = 0; e < 16; ++e) {
                float cv = mix4(sh.w.CmS[e * 32 + lane], al0, al1, al2, al3);
                C.Cts[lane * 17 + e] = cv;
                out[OFF_CT + bt * 512u + (unsigned)(e * 32 + lane)] = cv;
            }
#pragma unroll
            for (int e = 0; e < 8; ++e)
                out[OFF_BT + bt * 256u + (unsigned)(e * 32 + lane)] =
                    mix4(sh.w.BmS[e * 32 + lane], al0, al1, al2, al3);
        }
        CBAR();   // As ready (+ Ls from prev step already ordered)

        // ===== phase 1: G halves, S partials, mu, A_t out =====================
        if (cw == 0) {
            float m0 = 0.f, m1 = 0.f;
#pragma unroll 8
            for (int k = 0; k < 32; k += 2) {
                m0 = fmaf(ar[k],     __shfl_sync(FULLMASK, mu_own, k),     m0);
                m1 = fmaf(ar[k + 1], __shfl_sync(FULLMASK, mu_own, k + 1), m1);
            }
#pragma unroll
            for (int j = 0; j < 8; ++j) {
                float bj = mix4(sh.w.BmT[j * 32 + lane], al0, al1, al2, al3);
                m0 = fmaf(bj, __shfl_sync(FULLMASK, u_cur, j), m0);
            }
            mu_new = m0 + m1;
            out[OFF_MU + bt * 32u + lane] = mu_new;
#pragma unroll
            for (int i = 0; i < 16; ++i) g[i] = 0.f;
#pragma unroll 4
            for (int m = 0; m < 32; ++m) {
                float ak = ar[m];
                const float4* Lr = (const float4*)&C.Ls[m * 36];
#pragma unroll
                for (int i = 0; i < 4; ++i) {
                    float4 lv = Lr[i];
                    g[4*i+0] = fmaf(ak, lv.x, g[4*i+0]);
                    g[4*i+1] = fmaf(ak, lv.y, g[4*i+1]);
                    g[4*i+2] = fmaf(ak, lv.z, g[4*i+2]);
                    g[4*i+3] = fmaf(ak, lv.w, g[4*i+3]);
                }
            }
#pragma unroll
            for (int i = 0; i < 4; ++i)
                *(float4*)&C.Gs[lane * 36 + 4 * i] =
                    make_float4(g[4*i], g[4*i+1], g[4*i+2], g[4*i+3]);
            __syncwarp();
#pragma unroll 2
            for (int j = 0; j < 32; ++j) {
                const float4* Gr = (const float4*)&C.Gs[j * 36];
                float a0 = 0.f, a1 = 0.f, a2 = 0.f, a3 = 0.f;
#pragma unroll
                for (int i = 0; i < 4; ++i) {
                    float4 gv = Gr[i];
                    a0 = fmaf(g[4*i+0], gv.x, a0);
                    a1 = fmaf(g[4*i+1], gv.y, a1);
                    a2 = fmaf(g[4*i+2], gv.z, a2);
                    a3 = fmaf(g[4*i+3], gv.w, a3);
                }
                sreg[j] = (a0 + a1) + (a2 + a3);
                C.Ss0[lane * 33 + j] = sreg[j];
            }
        } else {
#pragma unroll 8
            for (int j = 0; j < 32; ++j)
                out[OFF_AT + bt * 1024u + (unsigned)(j * 32 + lane)] = C.As[j * 33 + lane];
#pragma unroll
            for (int i = 0; i < 16; ++i) g[i] = 0.f;
#pragma unroll 4
            for (int m = 0; m < 32; ++m) {
                float ak = C.As[lane * 33 + m];
                const float4* Lr = (const float4*)&C.Ls[m * 36 + 16];
#pragma unroll
                for (int i = 0; i < 4; ++i) {
                    float4 lv = Lr[i];
                    g[4*i+0] = fmaf(ak, lv.x, g[4*i+0]);
                    g[4*i+1] = fmaf(ak, lv.y, g[4*i+1]);
                    g[4*i+2] = fmaf(ak, lv.z, g[4*i+2]);
                    g[4*i+3] = fmaf(ak, lv.w, g[4*i+3]);
                }
            }
#pragma unroll
            for (int i = 0; i < 4; ++i)
                *(float4*)&C.Gs[lane * 36 + 16 + 4 * i] =
                    make_float4(g[4*i], g[4*i+1], g[4*i+2], g[4*i+3]);
            __syncwarp();
#pragma unroll 2
            for (int j = 0; j < 32; ++j) {
                const float4* Gr = (const float4*)&C.Gs[j * 36 + 16];
                float a0 = 0.f, a1 = 0.f, a2 = 0.f, a3 = 0.f;
#pragma unroll
                for (int i = 0; i < 4; ++i) {
                    float4 gv = Gr[i];
                    a0 = fmaf(g[4*i+0], gv.x, a0);
                    a1 = fmaf(g[4*i+1], gv.y, a1);
                    a2 = fmaf(g[4*i+2], gv.z, a2);
                    a3 = fmaf(g[4*i+3], gv.w, a3);
                }
                C.Ss1[lane * 33 + j] = (a0 + a1) + (a2 + a3);
            }
        }
        CBAR();   // S partials ready

        // ===== phase 2: W0 chol(+z)+gx  ||  W1 gh + Sigma stores ==============
        if (cw == 0) {
            float a[32];
#pragma unroll
            for (int k = 0; k < 32; ++k)
                a[k] = sreg[k] + C.Ss1[lane * 33 + k] + sh.w.QT[k * 32 + lane];
            z_own = chol_ls(a, ep_cur, mu_new, lane, C.Ls);
            out[OFF_Z + bt * 32u + lane] = z_own;
            float gxa[6];
#pragma unroll
            for (int m = 0; m < 6; ++m) gxa[m] = sh.w.bxs[lane + 32 * m];
#pragma unroll 4
            for (int k = 0; k < 32; ++k) {
                float zk = __shfl_sync(FULLMASK, z_own, k);
                const float* wr = &sh.w.Wx[k * 192 + lane];
#pragma unroll
                for (int m = 0; m < 6; ++m) gxa[m] = fmaf(zk, wr[32 * m], gxa[m]);
            }
#pragma unroll
            for (int m = 0; m < 6; ++m) C.gxs[lane + 32 * m] = gxa[m];
        } else {
#pragma unroll
            for (int m = 0; m < 6; ++m) gha[m] = sh.w.bhs[lane + 32 * m];
#pragma unroll 4
            for (int hh = 0; hh < 32; ++hh) {
                float hv = __shfl_sync(FULLMASK, hown0, hh);
                const float* wr = &sh.w.Wh[hh * 192 + lane];
#pragma unroll
                for (int m = 0; m < 6; ++m) gha[m] = fmaf(hv, wr[32 * m], gha[m]);
            }
#pragma unroll 4
            for (int hh = 0; hh < 32; ++hh) {
                float hv = __shfl_sync(FULLMASK, hown1, hh);
                const float* wr = &sh.w.Wh[(hh + 32) * 192 + lane];
#pragma unroll
                for (int m = 0; m < 6; ++m) gha[m] = fmaf(hv, wr[32 * m], gha[m]);
            }
#pragma unroll 4
            for (int j = 0; j < 32; ++j)
                out[OFF_SIG + bt * 1024u + (unsigned)(j * 32 + lane)] =
                    C.Ss0[lane * 33 + j] + C.Ss1[lane * 33 + j] + sh.w.QT[j * 32 + lane];
        }
        CBAR();   // gxs ready

        // ===== phase 3: W0 a_t + state roll  ||  W1 GRU + softmax =============
        if (cw == 0) {
            float acc = 0.f;
#pragma unroll 8
            for (int k = 0; k < 32; ++k) {
                float zk = __shfl_sync(FULLMASK, z_own, k);
                acc = fmaf(C.Cts[k * 17 + (lane & 15)], zk, acc);
            }
            if (lane < 16) out[OFF_A + bt * 16u + lane] = acc;
            mu_own = mu_new; ep_cur = ep_nxt; u_cur = u_nxt;
        } else {
            float gx0 = C.gxs[lane],      gx1 = C.gxs[lane + 32];
            float gx2 = C.gxs[lane + 64], gx3 = C.gxs[lane + 96];
            float gx4 = C.gxs[lane + 128],gx5 = C.gxs[lane + 160];
            float r0  = fast_sigmoid(gx0 + gha[0]);
            float r1  = fast_sigmoid(gx1 + gha[1]);
            float zg0 = fast_sigmoid(gx2 + gha[2]);
            float zg1 = fast_sigmoid(gx3 + gha[3]);
            float n0  = fast_tanh(gx4 + r0 * gha[4]);
            float n1  = fast_tanh(gx5 + r1 * gha[5]);
            hown0 = (1.f - zg0) * n0 + zg0 * hown0;
            hown1 = (1.f - zg1) * n1 + zg1 * hown1;
            float4 w0 = sh.w.Wo4[lane], w1 = sh.w.Wo4[lane + 32];
            float p0 = fmaf(hown0, w0.x, hown1 * w1.x);
            float p1 = fmaf(hown0, w0.y, hown1 * w1.y);
            float p2 = fmaf(hown0, w0.z, hown1 * w1.z);
            float p3 = fmaf(hown0, w0.w, hown1 * w1.w);
#pragma unroll
            for (int off = 16; off; off >>= 1) {
                p0 += __shfl_xor_sync(FULLMASK, p0, off);
                p1 += __shfl_xor_sync(FULLMASK, p1, off);
                p2 += __shfl_xor_sync(FULLMASK, p2, off);
                p3 += __shfl_xor_sync(FULLMASK, p3, off);
            }
            float o0 = p0 + bo0, o1 = p1 + bo1, o2 = p2 + bo2, o3 = p3 + bo3;
            float mx = fmaxf(fmaxf(o0, o1), fmaxf(o2, o3));
            float e0 = __expf(o0 - mx), e1 = __expf(o1 - mx);
            float e2 = __expf(o2 - mx), e3 = __expf(o3 - mx);
            float inv = 1.f / (e0 + e1 + e2 + e3);
            if (lane == 0) {
                C.alsh[0] = e0 * inv; C.alsh[1] = e1 * inv;
                C.alsh[2] = e2 * inv; C.alsh[3] = e3 * inv;
            }
        }
        CBAR();   // alpha ready
        al0 = C.alsh[0]; al1 = C.alsh[1]; al2 = C.alsh[2]; al3 = C.alsh[3];
    }
#undef CBAR
}

extern "C" void kernel_launch(void* const* d_in, const int* in_sizes, int n_in,
                              void* d_out, int out_size)
{
    size_t shbytes = sizeof(SAll);
    cudaFuncSetAttribute(lgssm_kernel,
                         cudaFuncAttributeMaxDynamicSharedMemorySize, (int)shbytes);
    lgssm_kernel<<<128, 128, shbytes>>>(
        (const float*)d_in[0],  (const float*)d_in[1],  (const float*)d_in[2],
        (const float*)d_in[3],  (const float*)d_in[4],  (const float*)d_in[5],
        (const float*)d_in[6],  (const float*)d_in[7],  (const float*)d_in[8],
        (const float*)d_in[9],  (const float*)d_in[10], (const float*)d_in[11],
        (const float*)d_in[12], (const float*)d_in[13], (const float*)d_in[14],
        (const float*)d_in[15], (float*)d_out);
}